// round 14
// baseline (speedup 1.0000x reference)
#include <cuda_runtime.h>

// EntropyLoss: heatmap [8, 20, 512, 512] f32 -> entropy [8] f32
//
// Per (n,c):  s = sum_{x>0} exp(x),  U = sum_{x>0} x*exp(x),  cnt = #positives
//             ent_c = (log s - U/s) / ln2          (max-shift cancels exactly)
// Per n:      out[n] = sum_c ent_c / sum_{c,hw} cnt
//
// R14 (consolidation): R4-R13 established a ~5.3TB/s streaming floor for
// this pattern, invariant to MLP(1-4), pipelining, TMA, load width, and L2
// hints (evict_last needs the persisting-L2 carveout, which the harness
// forbids changing). This kernel is the floor-form: R9's balanced geometry
// (3040 uniform segments, 1520 blocks x 128 = exactly 10 blocks on each of
// 152 SMs, one wave) + R4's low-issue branchy accumulate + single fused
// kernel with last-block finalize (counter self-resets for graph replay).

#define N_BATCH   8
#define N_CH      20
#define CHANNELS  (N_BATCH * N_CH)    // 160
#define HW        (512 * 512)         // 262144 elems/channel
#define HW4       (HW / 4)            // 65536 float4/channel
#define SPLIT     19                  // segments per channel
#define NSEG      (CHANNELS * SPLIT)  // 3040 segments, all equal-size
#define NBLK      1520                // 152 SMs x 10 blocks, single wave
#define TPB       128
#define NWARP     (TPB / 32)

__device__ float g_ps[NSEG];        // partial sum exp(x)
__device__ float g_pU[NSEG];        // partial sum x*exp(x)
__device__ float g_pc[NSEG];        // partial positive count
__device__ unsigned int g_done = 0; // arrival counter (reset by last block)

#define ACC4(v)                                                             \
    do {                                                                    \
        if ((v).x > 0.f) { float e = __expf((v).x); s += e; U = fmaf((v).x, e, U); cnt += 1.f; } \
        if ((v).y > 0.f) { float e = __expf((v).y); s += e; U = fmaf((v).y, e, U); cnt += 1.f; } \
        if ((v).z > 0.f) { float e = __expf((v).z); s += e; U = fmaf((v).z, e, U); cnt += 1.f; } \
        if ((v).w > 0.f) { float e = __expf((v).w); s += e; U = fmaf((v).w, e, U); cnt += 1.f; } \
    } while (0)

__global__ void __launch_bounds__(TPB, 10)
entropy_fused(const float* __restrict__ in, float* __restrict__ out)
{
    __shared__ float sh_s[2][NWARP], sh_U[2][NWARP], sh_c[2][NWARP];

    const int w = threadIdx.x >> 5;
    const int l = threadIdx.x & 31;

    // Two equal segments per block, from different channels (sg, sg+NBLK).
    #pragma unroll
    for (int sidx = 0; sidx < 2; sidx++) {
        const int sg  = blockIdx.x + sidx * NBLK;   // 0..3039
        const int ch  = sg / SPLIT;                 // 0..159
        const int seg = sg % SPLIT;
        const int i0  = (int)(((long long)HW4 * seg) / SPLIT);
        const int i1  = (int)(((long long)HW4 * (seg + 1)) / SPLIT);
        const float4* __restrict__ p4 =
            reinterpret_cast<const float4*>(in + (size_t)ch * HW);

        float s = 0.f, U = 0.f, cnt = 0.f;

        #pragma unroll 4
        for (int i = i0 + threadIdx.x; i < i1; i += TPB) {
            float4 v = p4[i];
            ACC4(v);
        }

        // warp reduce
        #pragma unroll
        for (int o = 16; o > 0; o >>= 1) {
            s   += __shfl_down_sync(0xffffffffu, s,   o);
            U   += __shfl_down_sync(0xffffffffu, U,   o);
            cnt += __shfl_down_sync(0xffffffffu, cnt, o);
        }
        if (l == 0) { sh_s[sidx][w] = s; sh_U[sidx][w] = U; sh_c[sidx][w] = cnt; }
    }

    __syncthreads();   // one sync covers both segments' shared writes

    __shared__ bool is_last;
    if (threadIdx.x == 0) {
        #pragma unroll
        for (int sidx = 0; sidx < 2; sidx++) {
            float ts = 0.f, tU = 0.f, tc = 0.f;
            #pragma unroll
            for (int k = 0; k < NWARP; k++) {
                ts += sh_s[sidx][k]; tU += sh_U[sidx][k]; tc += sh_c[sidx][k];
            }
            const int sg = blockIdx.x + sidx * NBLK;
            g_ps[sg] = ts; g_pU[sg] = tU; g_pc[sg] = tc;
        }
        __threadfence();                       // publish partials before arrival
        unsigned int old = atomicAdd(&g_done, 1u);
        is_last = (old == NBLK - 1);
    }
    __syncthreads();
    if (!is_last) return;

    // ---- finalize: only the last-arriving block runs this ----
    __threadfence();                           // acquire: see all partials

    __shared__ float ent_c[CHANNELS];
    __shared__ float cnt_c[CHANNELS];

    const int t = threadIdx.x;
    if (t == 0) g_done = 0;                    // reset for next graph replay
    for (int c = t; c < CHANNELS; c += TPB) {
        float ss = 0.f, UU = 0.f, cc = 0.f;
        #pragma unroll
        for (int k = 0; k < SPLIT; k++) {
            ss += g_ps[c * SPLIT + k];
            UU += g_pU[c * SPLIT + k];
            cc += g_pc[c * SPLIT + k];
        }
        float ent = 0.f;
        if (ss > 0.f) {
            const float INV_LN2 = 1.4426950408889634f;
            ent = (logf(ss) - UU / ss) * INV_LN2;
        }
        ent_c[c] = ent;
        cnt_c[c] = cc;
    }
    __syncthreads();

    if (t < N_BATCH) {
        float es = 0.f, cs = 0.f;
        #pragma unroll
        for (int c = 0; c < N_CH; c++) {
            es += ent_c[t * N_CH + c];
            cs += cnt_c[t * N_CH + c];
        }
        out[t] = es / cs;
    }
}

extern "C" void kernel_launch(void* const* d_in, const int* in_sizes, int n_in,
                              void* d_out, int out_size)
{
    const float* heatmap = (const float*)d_in[0];
    float* out = (float*)d_out;
    entropy_fused<<<NBLK, TPB>>>(heatmap, out);
}

// round 16
// speedup vs baseline: 1.1223x; 1.1223x over previous
#include <cuda_runtime.h>

// EntropyLoss: heatmap [8, 20, 512, 512] f32 -> entropy [8] f32
//
// Per (n,c):  s = sum_{x>0} exp(x),  U = sum_{x>0} x*exp(x),  cnt = #positives
//             ent_c = (log s - U/s) / ln2          (max-shift cancels exactly)
// Per n:      out[n] = sum_c ent_c / sum_{c,hw} cnt
//
// R15 = R6 verbatim (fastest measured kernel: 32.35us, DRAM 66.9%).
// R4-R14 established the platform streaming floor ~5.3TB/s (LTS cap at
// DVFS-throttled clocks), invariant to MLP, pipelining, TMA, load width,
// and L2 hints. This is the floor-form kernel.

#define N_BATCH   8
#define N_CH      20
#define CHANNELS  (N_BATCH * N_CH)   // 160
#define HW        (512 * 512)        // 262144 elems/channel
#define HW4       (HW / 4)           // 65536 float4/channel
#define SPLIT     11                 // segments per channel
#define NBLK      (CHANNELS * SPLIT) // 1760 blocks (cap 148*12=1776)
#define TPB       128

__device__ float g_ps[NBLK];        // partial sum exp(x)
__device__ float g_pU[NBLK];        // partial sum x*exp(x)
__device__ float g_pc[NBLK];        // partial positive count
__device__ unsigned int g_done = 0; // arrival counter (reset by last block)

// Branchless per-float4 accumulate (SEL, no branches)
#define ACC4(v)                                                   \
    do {                                                          \
        float e0 = __expf((v).x); float e1 = __expf((v).y);       \
        float e2 = __expf((v).z); float e3 = __expf((v).w);       \
        e0 = ((v).x > 0.f) ? e0 : 0.f;                            \
        e1 = ((v).y > 0.f) ? e1 : 0.f;                            \
        e2 = ((v).z > 0.f) ? e2 : 0.f;                            \
        e3 = ((v).w > 0.f) ? e3 : 0.f;                            \
        s += e0; U = fmaf((v).x, e0, U);                          \
        s += e1; U = fmaf((v).y, e1, U);                          \
        s += e2; U = fmaf((v).z, e2, U);                          \
        s += e3; U = fmaf((v).w, e3, U);                          \
        cnt += ((v).x > 0.f) ? 1.f : 0.f;                         \
        cnt += ((v).y > 0.f) ? 1.f : 0.f;                         \
        cnt += ((v).z > 0.f) ? 1.f : 0.f;                         \
        cnt += ((v).w > 0.f) ? 1.f : 0.f;                         \
    } while (0)

__global__ void __launch_bounds__(TPB, 12)
entropy_fused(const float* __restrict__ in, float* __restrict__ out)
{
    const int b   = blockIdx.x;
    const int ch  = b / SPLIT;        // 0..159
    const int seg = b % SPLIT;
    const int i0  = (int)(((long long)HW4 * seg) / SPLIT);
    const int i1  = (int)(((long long)HW4 * (seg + 1)) / SPLIT);
    const float4* __restrict__ p4 =
        reinterpret_cast<const float4*>(in + (size_t)ch * HW);

    float s = 0.f, U = 0.f, cnt = 0.f;

    int i = i0 + threadIdx.x;
    // main loop: 4 independent LDG.128 in flight per warp
    #pragma unroll 1
    for (; i + 3 * TPB < i1; i += 4 * TPB) {
        float4 a = __ldcs(p4 + i);
        float4 bb = __ldcs(p4 + i + TPB);
        float4 c = __ldcs(p4 + i + 2 * TPB);
        float4 d = __ldcs(p4 + i + 3 * TPB);
        ACC4(a); ACC4(bb); ACC4(c); ACC4(d);
    }
    // tail
    for (; i < i1; i += TPB) {
        float4 a = __ldcs(p4 + i);
        ACC4(a);
    }

    // warp reduce
    #pragma unroll
    for (int o = 16; o > 0; o >>= 1) {
        s   += __shfl_down_sync(0xffffffffu, s,   o);
        U   += __shfl_down_sync(0xffffffffu, U,   o);
        cnt += __shfl_down_sync(0xffffffffu, cnt, o);
    }

    __shared__ float sh_s[TPB / 32], sh_U[TPB / 32], sh_c[TPB / 32];
    const int w = threadIdx.x >> 5;
    const int l = threadIdx.x & 31;
    if (l == 0) { sh_s[w] = s; sh_U[w] = U; sh_c[w] = cnt; }
    __syncthreads();

    __shared__ bool is_last;
    if (threadIdx.x == 0) {
        float ts = 0.f, tU = 0.f, tc = 0.f;
        #pragma unroll
        for (int k = 0; k < TPB / 32; k++) { ts += sh_s[k]; tU += sh_U[k]; tc += sh_c[k]; }
        g_ps[b] = ts; g_pU[b] = tU; g_pc[b] = tc;
        __threadfence();                       // publish partials before arrival
        unsigned int old = atomicAdd(&g_done, 1u);
        is_last = (old == NBLK - 1);
    }
    __syncthreads();
    if (!is_last) return;

    // ---- finalize: only the last-arriving block runs this ----
    __threadfence();                           // acquire: see all partials

    __shared__ float ent_c[CHANNELS];
    __shared__ float cnt_c[CHANNELS];

    const int t = threadIdx.x;
    if (t == 0) g_done = 0;                    // reset for next graph replay
    // 128 threads, 160 channels: two passes
    for (int c = t; c < CHANNELS; c += TPB) {
        float ss = 0.f, UU = 0.f, cc = 0.f;
        #pragma unroll
        for (int k = 0; k < SPLIT; k++) {
            ss += g_ps[c * SPLIT + k];
            UU += g_pU[c * SPLIT + k];
            cc += g_pc[c * SPLIT + k];
        }
        float ent = 0.f;
        if (ss > 0.f) {
            const float INV_LN2 = 1.4426950408889634f;
            ent = (logf(ss) - UU / ss) * INV_LN2;
        }
        ent_c[c] = ent;
        cnt_c[c] = cc;
    }
    __syncthreads();

    if (t < N_BATCH) {
        float es = 0.f, cs = 0.f;
        #pragma unroll
        for (int c = 0; c < N_CH; c++) {
            es += ent_c[t * N_CH + c];
            cs += cnt_c[t * N_CH + c];
        }
        out[t] = es / cs;
    }
}

extern "C" void kernel_launch(void* const* d_in, const int* in_sizes, int n_in,
                              void* d_out, int out_size)
{
    const float* heatmap = (const float*)d_in[0];
    float* out = (float*)d_out;
    entropy_fused<<<NBLK, TPB>>>(heatmap, out);
}

// round 17
// speedup vs baseline: 1.1298x; 1.0067x over previous
#include <cuda_runtime.h>

// EntropyLoss: heatmap [8, 20, 512, 512] f32 -> entropy [8] f32
//
// Per (n,c):  s = sum_{x>0} exp(x),  U = sum_{x>0} x*exp(x),  cnt = #positives
//             ent_c = (log s - U/s) / ln2          (max-shift cancels exactly)
// Per n:      out[n] = sum_c ent_c / sum_{c,hw} cnt
//
// R17 = R6 (floor-form: 32.0us kernel, DRAM 67.6%) with the count path
// reduced to a predicated integer increment (removes 1 instr/element of
// the SEL+FADD pair; int warp-reduce, convert to float after). R4-R16
// established the ~5.3TB/s streaming ceiling invariant to MLP, pipelining,
// TMA, load width, and L2 hints — this targets issue slots / DVFS headroom.

#define N_BATCH   8
#define N_CH      20
#define CHANNELS  (N_BATCH * N_CH)   // 160
#define HW        (512 * 512)        // 262144 elems/channel
#define HW4       (HW / 4)           // 65536 float4/channel
#define SPLIT     11                 // segments per channel
#define NBLK      (CHANNELS * SPLIT) // 1760 blocks
#define TPB       128

__device__ float g_ps[NBLK];        // partial sum exp(x)
__device__ float g_pU[NBLK];        // partial sum x*exp(x)
__device__ float g_pc[NBLK];        // partial positive count
__device__ unsigned int g_done = 0; // arrival counter (reset by last block)

// Branchless accumulate; count via predicated integer increment.
#define ACC4(v)                                                   \
    do {                                                          \
        float e0 = __expf((v).x); float e1 = __expf((v).y);       \
        float e2 = __expf((v).z); float e3 = __expf((v).w);       \
        bool p0 = (v).x > 0.f, p1 = (v).y > 0.f;                  \
        bool p2 = (v).z > 0.f, p3 = (v).w > 0.f;                  \
        e0 = p0 ? e0 : 0.f;                                       \
        e1 = p1 ? e1 : 0.f;                                       \
        e2 = p2 ? e2 : 0.f;                                       \
        e3 = p3 ? e3 : 0.f;                                       \
        s += e0; U = fmaf((v).x, e0, U);                          \
        s += e1; U = fmaf((v).y, e1, U);                          \
        s += e2; U = fmaf((v).z, e2, U);                          \
        s += e3; U = fmaf((v).w, e3, U);                          \
        cnt_i += (int)p0; cnt_i += (int)p1;                       \
        cnt_i += (int)p2; cnt_i += (int)p3;                       \
    } while (0)

__global__ void __launch_bounds__(TPB, 12)
entropy_fused(const float* __restrict__ in, float* __restrict__ out)
{
    const int b   = blockIdx.x;
    const int ch  = b / SPLIT;        // 0..159
    const int seg = b % SPLIT;
    const int i0  = (int)(((long long)HW4 * seg) / SPLIT);
    const int i1  = (int)(((long long)HW4 * (seg + 1)) / SPLIT);
    const float4* __restrict__ p4 =
        reinterpret_cast<const float4*>(in + (size_t)ch * HW);

    float s = 0.f, U = 0.f;
    int cnt_i = 0;

    int i = i0 + threadIdx.x;
    // main loop: 4 independent LDG.128 in flight per warp
    #pragma unroll 1
    for (; i + 3 * TPB < i1; i += 4 * TPB) {
        float4 a = __ldcs(p4 + i);
        float4 bb = __ldcs(p4 + i + TPB);
        float4 c = __ldcs(p4 + i + 2 * TPB);
        float4 d = __ldcs(p4 + i + 3 * TPB);
        ACC4(a); ACC4(bb); ACC4(c); ACC4(d);
    }
    // tail
    for (; i < i1; i += TPB) {
        float4 a = __ldcs(p4 + i);
        ACC4(a);
    }

    // warp reduce (float sums + exact int count)
    #pragma unroll
    for (int o = 16; o > 0; o >>= 1) {
        s     += __shfl_down_sync(0xffffffffu, s,     o);
        U     += __shfl_down_sync(0xffffffffu, U,     o);
        cnt_i += __shfl_down_sync(0xffffffffu, cnt_i, o);
    }
    float cnt = (float)cnt_i;

    __shared__ float sh_s[TPB / 32], sh_U[TPB / 32], sh_c[TPB / 32];
    const int w = threadIdx.x >> 5;
    const int l = threadIdx.x & 31;
    if (l == 0) { sh_s[w] = s; sh_U[w] = U; sh_c[w] = cnt; }
    __syncthreads();

    __shared__ bool is_last;
    if (threadIdx.x == 0) {
        float ts = 0.f, tU = 0.f, tc = 0.f;
        #pragma unroll
        for (int k = 0; k < TPB / 32; k++) { ts += sh_s[k]; tU += sh_U[k]; tc += sh_c[k]; }
        g_ps[b] = ts; g_pU[b] = tU; g_pc[b] = tc;
        __threadfence();                       // publish partials before arrival
        unsigned int old = atomicAdd(&g_done, 1u);
        is_last = (old == NBLK - 1);
    }
    __syncthreads();
    if (!is_last) return;

    // ---- finalize: only the last-arriving block runs this ----
    __threadfence();                           // acquire: see all partials

    __shared__ float ent_c[CHANNELS];
    __shared__ float cnt_c[CHANNELS];

    const int t = threadIdx.x;
    if (t == 0) g_done = 0;                    // reset for next graph replay
    // 128 threads, 160 channels: two passes
    for (int c = t; c < CHANNELS; c += TPB) {
        float ss = 0.f, UU = 0.f, cc = 0.f;
        #pragma unroll
        for (int k = 0; k < SPLIT; k++) {
            ss += g_ps[c * SPLIT + k];
            UU += g_pU[c * SPLIT + k];
            cc += g_pc[c * SPLIT + k];
        }
        float ent = 0.f;
        if (ss > 0.f) {
            const float INV_LN2 = 1.4426950408889634f;
            ent = (logf(ss) - UU / ss) * INV_LN2;
        }
        ent_c[c] = ent;
        cnt_c[c] = cc;
    }
    __syncthreads();

    if (t < N_BATCH) {
        float es = 0.f, cs = 0.f;
        #pragma unroll
        for (int c = 0; c < N_CH; c++) {
            es += ent_c[t * N_CH + c];
            cs += cnt_c[t * N_CH + c];
        }
        out[t] = es / cs;
    }
}

extern "C" void kernel_launch(void* const* d_in, const int* in_sizes, int n_in,
                              void* d_out, int out_size)
{
    const float* heatmap = (const float*)d_in[0];
    float* out = (float*)d_out;
    entropy_fused<<<NBLK, TPB>>>(heatmap, out);
}